// round 3
// baseline (speedup 1.0000x reference)
#include <cuda_runtime.h>
#include <math.h>

#define BB 8
#define SS 4096
#define NR (BB*SS)      // 32768 rows
#define EE 512
#define MF 256
#define SPLITK 8

// ---------------- scratch (device globals; no allocation allowed) ----------
__device__ float g_xn [(size_t)NR*EE];
__device__ float g_q  [(size_t)NR*EE];
__device__ float g_k  [(size_t)NR*EE];
__device__ float g_v  [(size_t)NR*EE];
__device__ float g_y  [(size_t)NR*EE];
__device__ float g_qp [(size_t)NR*MF];
__device__ float g_kp [(size_t)NR*MF];
__device__ float g_xdq[NR];
__device__ float g_xdk[NR];
__device__ float g_D  [NR];
__device__ float g_ks [BB*MF];
__device__ float g_kptv [(size_t)BB*EE*MF];
__device__ float g_kptvp[(size_t)SPLITK*BB*EE*MF];

// ---------------- LayerNorm: one block per row of 512 ---------------------
__global__ __launch_bounds__(128) void ln_kernel(
    const float* __restrict__ x, const float* __restrict__ gamma,
    const float* __restrict__ beta, float* __restrict__ out)
{
    int row = blockIdx.x;
    const float4* xr = reinterpret_cast<const float4*>(x + (size_t)row*EE);
    int t = threadIdx.x;
    float4 v = xr[t];
    float s  = v.x+v.y+v.z+v.w;
    float s2 = v.x*v.x+v.y*v.y+v.z*v.z+v.w*v.w;
    #pragma unroll
    for (int o=16;o>0;o>>=1){
        s  += __shfl_xor_sync(0xffffffffu, s,  o);
        s2 += __shfl_xor_sync(0xffffffffu, s2, o);
    }
    __shared__ float rs[4], rs2[4];
    int wid = t>>5, lane = t&31;
    if (lane==0){ rs[wid]=s; rs2[wid]=s2; }
    __syncthreads();
    s  = rs[0]+rs[1]+rs[2]+rs[3];
    s2 = rs2[0]+rs2[1]+rs2[2]+rs2[3];
    float mu  = s * (1.f/EE);
    float var = s2*(1.f/EE) - mu*mu;
    float inv = rsqrtf(var + 1e-5f);
    float4 g  = reinterpret_cast<const float4*>(gamma)[t];
    float4 bt = reinterpret_cast<const float4*>(beta)[t];
    float4 o;
    o.x = (v.x-mu)*inv*g.x + bt.x;
    o.y = (v.y-mu)*inv*g.y + bt.y;
    o.z = (v.z-mu)*inv*g.z + bt.z;
    o.w = (v.w-mu)*inv*g.w + bt.w;
    reinterpret_cast<float4*>(out + (size_t)row*EE)[t] = o;
}

// ---------------- NT GEMM: C[r,c] = sum_k A[r,k]*W[c,k] + epilogue --------
// MODE 0: + bias[c]
// MODE 1: expf(acc - xd[r]) * (1/16)
// MODE 2: acc / (D[r] + 1e-8)        (per-batch via blockIdx.z strides)
// MODE 3: + bias[c] + addsrc[r,c]
template<int MODE>
__global__ __launch_bounds__(256) void gemm_nt(
    const float* __restrict__ A, const float* __restrict__ W, float* __restrict__ C,
    int K, int ncols,
    const float* __restrict__ bias, const float* __restrict__ xd,
    const float* __restrict__ Dv, const float* __restrict__ addsrc,
    size_t aB, size_t wB, size_t cB, int dB)
{
    __shared__ float As[8][128];
    __shared__ float Ws[8][128];
    int z = blockIdx.z;
    A += (size_t)z*aB; W += (size_t)z*wB; C += (size_t)z*cB;
    const float* Dz = (MODE==2) ? (Dv + (size_t)z*dB) : nullptr;

    int tid = threadIdx.x;
    int rowBase = blockIdx.x*128;
    int colBase = blockIdx.y*128;
    int lr = tid>>1;          // 0..127
    int lk = (tid&1)*4;       // 0 or 4
    int ty = tid>>4, tx = tid&15;

    float acc[8][8];
    #pragma unroll
    for (int i=0;i<8;i++)
        #pragma unroll
        for (int j=0;j<8;j++) acc[i][j]=0.f;

    const float* Aptr = A + (size_t)(rowBase+lr)*K + lk;
    const float* Wptr = W + (size_t)(colBase+lr)*K + lk;

    for (int k0=0;k0<K;k0+=8){
        float4 av = *reinterpret_cast<const float4*>(Aptr + k0);
        float4 wv = *reinterpret_cast<const float4*>(Wptr + k0);
        __syncthreads();
        As[lk+0][lr]=av.x; As[lk+1][lr]=av.y; As[lk+2][lr]=av.z; As[lk+3][lr]=av.w;
        Ws[lk+0][lr]=wv.x; Ws[lk+1][lr]=wv.y; Ws[lk+2][lr]=wv.z; Ws[lk+3][lr]=wv.w;
        __syncthreads();
        #pragma unroll
        for (int kk=0;kk<8;kk++){
            float a[8], b[8];
            *(float4*)&a[0] = *(const float4*)&As[kk][ty*8];
            *(float4*)&a[4] = *(const float4*)&As[kk][ty*8+4];
            *(float4*)&b[0] = *(const float4*)&Ws[kk][tx*8];
            *(float4*)&b[4] = *(const float4*)&Ws[kk][tx*8+4];
            #pragma unroll
            for (int i=0;i<8;i++)
                #pragma unroll
                for (int j=0;j<8;j++)
                    acc[i][j] = fmaf(a[i], b[j], acc[i][j]);
        }
    }

    #pragma unroll
    for (int i=0;i<8;i++){
        int r = rowBase + ty*8 + i;
        float xv=0.f, dinv=1.f;
        if (MODE==1) xv = xd[r];
        if (MODE==2) dinv = 1.f/(Dz[r]+1e-8f);
        #pragma unroll
        for (int j=0;j<8;j+=4){
            int c = colBase + tx*8 + j;
            float* ap = &acc[i][j];
            float4 o;
            if (MODE==0){
                float4 bv = *reinterpret_cast<const float4*>(bias + c);
                o.x=ap[0]+bv.x; o.y=ap[1]+bv.y; o.z=ap[2]+bv.z; o.w=ap[3]+bv.w;
            } else if (MODE==1){
                o.x=expf(ap[0]-xv)*0.0625f; o.y=expf(ap[1]-xv)*0.0625f;
                o.z=expf(ap[2]-xv)*0.0625f; o.w=expf(ap[3]-xv)*0.0625f;
            } else if (MODE==2){
                o.x=ap[0]*dinv; o.y=ap[1]*dinv; o.z=ap[2]*dinv; o.w=ap[3]*dinv;
            } else {
                float4 bv = *reinterpret_cast<const float4*>(bias + c);
                float4 sv = *reinterpret_cast<const float4*>(addsrc + (size_t)r*ncols + c);
                o.x=ap[0]+bv.x+sv.x; o.y=ap[1]+bv.y+sv.y;
                o.z=ap[2]+bv.z+sv.z; o.w=ap[3]+bv.w+sv.w;
            }
            *reinterpret_cast<float4*>(C + (size_t)r*ncols + c) = o;
        }
    }
}

// ---------------- 0.5*||row||^2 for q and k --------------------------------
__global__ __launch_bounds__(256) void xd_kernel(
    const float* __restrict__ q, const float* __restrict__ k,
    float* __restrict__ xdq, float* __restrict__ xdk)
{
    int row  = blockIdx.x*8 + (threadIdx.x>>5);
    int lane = threadIdx.x&31;
    const float4* qr = reinterpret_cast<const float4*>(q + (size_t)row*EE);
    const float4* kr = reinterpret_cast<const float4*>(k + (size_t)row*EE);
    float sq=0.f, sk=0.f;
    #pragma unroll
    for (int j=0;j<4;j++){
        float4 a = qr[lane + j*32];
        sq += a.x*a.x+a.y*a.y+a.z*a.z+a.w*a.w;
        float4 b = kr[lane + j*32];
        sk += b.x*b.x+b.y*b.y+b.z*b.z+b.w*b.w;
    }
    #pragma unroll
    for (int o=16;o>0;o>>=1){
        sq += __shfl_xor_sync(0xffffffffu, sq, o);
        sk += __shfl_xor_sync(0xffffffffu, sk, o);
    }
    if (lane==0){ xdq[row]=0.5f*sq; xdk[row]=0.5f*sk; }
}

// ---------------- column sums of kp per batch ------------------------------
__global__ __launch_bounds__(256) void ksum_kernel(
    const float* __restrict__ kp, float* __restrict__ out)
{
    int b = blockIdx.x, m0 = blockIdx.y*64;
    int tx = threadIdx.x & 63, ty = threadIdx.x >> 6;
    const float* base = kp + (size_t)b*SS*MF + m0 + tx;
    float s=0.f;
    for (int srow=ty; srow<SS; srow+=4) s += base[(size_t)srow*MF];
    __shared__ float red[4][64];
    red[ty][tx]=s;
    __syncthreads();
    if (ty==0) out[b*MF+m0+tx] = red[0][tx]+red[1][tx]+red[2][tx]+red[3][tx];
}

// ---------------- TN GEMM (split-K): kptv[b,e,m] = sum_s v[b,s,e]*kp[b,s,m]
__global__ __launch_bounds__(256) void gemm_tn_kptv(
    const float* __restrict__ Vm, const float* __restrict__ KP,
    float* __restrict__ Cp)
{
    int eBase = blockIdx.x*128;
    int mBase = blockIdx.y*128;
    int b  = blockIdx.z >> 3;   // SPLITK = 8
    int sk = blockIdx.z & 7;
    const float* Vb = Vm + (size_t)b*SS*EE;
    const float* Kb = KP + (size_t)b*SS*MF;
    int s0 = sk*(SS/SPLITK);
    __shared__ float As[8][128], Bs[8][128];
    int tid = threadIdx.x;
    int kr = tid>>5;
    int c4 = (tid&31)*4;
    int ty = tid>>4, tx = tid&15;

    float acc[8][8];
    #pragma unroll
    for (int i=0;i<8;i++)
        #pragma unroll
        for (int j=0;j<8;j++) acc[i][j]=0.f;

    for (int kk=0; kk<SS/SPLITK; kk+=8){
        int s = s0 + kk + kr;
        float4 av = *reinterpret_cast<const float4*>(Vb + (size_t)s*EE + eBase + c4);
        float4 bv = *reinterpret_cast<const float4*>(Kb + (size_t)s*MF + mBase + c4);
        __syncthreads();
        *(float4*)&As[kr][c4] = av;
        *(float4*)&Bs[kr][c4] = bv;
        __syncthreads();
        #pragma unroll
        for (int q8=0;q8<8;q8++){
            float a[8], b8[8];
            *(float4*)&a[0]  = *(const float4*)&As[q8][ty*8];
            *(float4*)&a[4]  = *(const float4*)&As[q8][ty*8+4];
            *(float4*)&b8[0] = *(const float4*)&Bs[q8][tx*8];
            *(float4*)&b8[4] = *(const float4*)&Bs[q8][tx*8+4];
            #pragma unroll
            for (int i=0;i<8;i++)
                #pragma unroll
                for (int j=0;j<8;j++)
                    acc[i][j] = fmaf(a[i], b8[j], acc[i][j]);
        }
    }
    float* Co = Cp + ((size_t)sk*BB + b)*EE*MF;
    #pragma unroll
    for (int i=0;i<8;i++){
        int e = eBase + ty*8 + i;
        #pragma unroll
        for (int j=0;j<8;j+=4){
            int m = mBase + tx*8 + j;
            *reinterpret_cast<float4*>(Co + (size_t)e*MF + m) =
                make_float4(acc[i][j],acc[i][j+1],acc[i][j+2],acc[i][j+3]);
        }
    }
}

__global__ __launch_bounds__(256) void reduce_kptv(
    const float* __restrict__ p, float* __restrict__ o)
{
    size_t i = (size_t)blockIdx.x*256 + threadIdx.x;
    const size_t st = (size_t)BB*EE*MF;
    float s = 0.f;
    #pragma unroll
    for (int sk=0;sk<SPLITK;sk++) s += p[(size_t)sk*st + i];
    o[i] = s;
}

// ---------------- D[r] = qp[r,:] . ksum[b,:] -------------------------------
__global__ __launch_bounds__(256) void d_kernel(
    const float* __restrict__ qp, const float* __restrict__ ks,
    float* __restrict__ D)
{
    int row  = blockIdx.x*8 + (threadIdx.x>>5);
    int lane = threadIdx.x&31;
    int b = row >> 12;  // row / 4096
    const float4* qr = reinterpret_cast<const float4*>(qp + (size_t)row*MF);
    const float4* kr = reinterpret_cast<const float4*>(ks + b*MF);
    float s=0.f;
    #pragma unroll
    for (int j=0;j<2;j++){
        float4 a=qr[lane+j*32], c=kr[lane+j*32];
        s += a.x*c.x + a.y*c.y + a.z*c.z + a.w*c.w;
    }
    #pragma unroll
    for (int o=16;o>0;o>>=1) s += __shfl_xor_sync(0xffffffffu, s, o);
    if (lane==0) D[row]=s;
}

// ---------------- launch ---------------------------------------------------
extern "C" void kernel_launch(void* const* d_in, const int* in_sizes, int n_in,
                              void* d_out, int out_size)
{
    const float* x     = (const float*)d_in[0];
    const float* qw    = (const float*)d_in[1];
    const float* qb    = (const float*)d_in[2];
    const float* kw    = (const float*)d_in[3];
    const float* kb    = (const float*)d_in[4];
    const float* vw    = (const float*)d_in[5];
    const float* vb    = (const float*)d_in[6];
    const float* pw    = (const float*)d_in[7];
    const float* pb    = (const float*)d_in[8];
    const float* gamma = (const float*)d_in[9];
    const float* beta  = (const float*)d_in[10];
    const float* w     = (const float*)d_in[11];
    float* out = (float*)d_out;

    float *xn,*q,*k,*v,*y,*qp,*kp,*xdq,*xdk,*D,*ks,*kptv,*kptvp;
    cudaGetSymbolAddress((void**)&xn,   g_xn);
    cudaGetSymbolAddress((void**)&q,    g_q);
    cudaGetSymbolAddress((void**)&k,    g_k);
    cudaGetSymbolAddress((void**)&v,    g_v);
    cudaGetSymbolAddress((void**)&y,    g_y);
    cudaGetSymbolAddress((void**)&qp,   g_qp);
    cudaGetSymbolAddress((void**)&kp,   g_kp);
    cudaGetSymbolAddress((void**)&xdq,  g_xdq);
    cudaGetSymbolAddress((void**)&xdk,  g_xdk);
    cudaGetSymbolAddress((void**)&D,    g_D);
    cudaGetSymbolAddress((void**)&ks,   g_ks);
    cudaGetSymbolAddress((void**)&kptv, g_kptv);
    cudaGetSymbolAddress((void**)&kptvp,g_kptvp);

    dim3 blk(256);

    // 1) LayerNorm
    ln_kernel<<<NR,128>>>(x, gamma, beta, xn);

    // 2) q/k/v projections (NT, K=512, 512 cols)
    dim3 gqkv(NR/128, EE/128, 1);
    gemm_nt<0><<<gqkv,blk>>>(xn, qw, q, EE, EE, qb, nullptr, nullptr, nullptr, 0,0,0,0);
    gemm_nt<0><<<gqkv,blk>>>(xn, kw, k, EE, EE, kb, nullptr, nullptr, nullptr, 0,0,0,0);
    gemm_nt<0><<<gqkv,blk>>>(xn, vw, v, EE, EE, vb, nullptr, nullptr, nullptr, 0,0,0,0);

    // 3) row half-norms
    xd_kernel<<<NR/8,256>>>(q, k, xdq, xdk);

    // 4) qp/kp random features (NT, K=512, 256 cols, exp epilogue)
    dim3 gqp(NR/128, MF/128, 1);
    gemm_nt<1><<<gqp,blk>>>(q, w, qp, EE, MF, nullptr, xdq, nullptr, nullptr, 0,0,0,0);
    gemm_nt<1><<<gqp,blk>>>(k, w, kp, EE, MF, nullptr, xdk, nullptr, nullptr, 0,0,0,0);

    // 5) ksum[b,m]
    ksum_kernel<<<dim3(BB, MF/64),blk>>>(kp, ks);

    // 6) kptv[b,e,m] via split-K partials (deterministic), then reduce
    gemm_tn_kptv<<<dim3(EE/128, MF/128, BB*SPLITK),blk>>>(v, kp, kptvp);
    reduce_kptv<<<((size_t)BB*EE*MF)/256,blk>>>(kptvp, kptv);

    // 7) D[r]
    d_kernel<<<NR/8,256>>>(qp, ks, D);

    // 8) y[b,s,e] = (qp @ kptv^T) / (D + eps)   (per-batch NT, K=256)
    dim3 gy(SS/128, EE/128, BB);
    gemm_nt<2><<<gy,blk>>>(qp, kptv, y, MF, EE, nullptr, nullptr, D, nullptr,
                           (size_t)SS*MF, (size_t)EE*MF, (size_t)SS*EE, SS);

    // 9) out = v + y @ pw^T + pb
    gemm_nt<3><<<gqkv,blk>>>(y, pw, out, EE, EE, pb, nullptr, nullptr, v, 0,0,0,0);
}

// round 5
// speedup vs baseline: 1.9655x; 1.9655x over previous
#include <cuda_runtime.h>
#include <math.h>
#include <stdint.h>

#define BB 8
#define SS 4096
#define NR (BB*SS)      // 32768 rows
#define EE 512
#define MF 256
#define SPLITK 8
#define NSTAGE 3
#define KC 32                       // k floats per chunk
#define STG_FLT 8192                // floats per stage: A 128*32 + B 128*32
#define SMEM_BYTES (NSTAGE*STG_FLT*4)

// ---------------- scratch (device globals; no allocation allowed) ----------
__device__ float g_xn [(size_t)NR*EE];
__device__ float g_q  [(size_t)NR*EE];
__device__ float g_k  [(size_t)NR*EE];
__device__ float g_v  [(size_t)NR*EE];
__device__ float g_y  [(size_t)NR*EE];
__device__ float g_vt [(size_t)NR*EE];   // [b][E][S]
__device__ float g_qp [(size_t)NR*MF];
__device__ float g_kp [(size_t)NR*MF];
__device__ float g_kpt[(size_t)NR*MF];   // [b][M][S]
__device__ float g_xdq[NR];
__device__ float g_xdk[NR];
__device__ float g_D  [NR];
__device__ float g_ks [BB*MF];
__device__ float g_kptv [(size_t)BB*EE*MF];
__device__ float g_kptvp[(size_t)SPLITK*BB*EE*MF];

// =================== portable tensor-core helpers (sm_80+) =================
__device__ __forceinline__ uint32_t f2tf(float f){
    uint32_t r; asm("cvt.rna.tf32.f32 %0, %1;" : "=r"(r) : "f"(f)); return r;
}
__device__ __forceinline__ void mma8(float* d, const uint32_t* a, const uint32_t* b){
    asm volatile("mma.sync.aligned.m16n8k8.row.col.f32.tf32.tf32.f32 "
        "{%0,%1,%2,%3}, {%4,%5,%6,%7}, {%8,%9}, {%0,%1,%2,%3};"
        : "+f"(d[0]), "+f"(d[1]), "+f"(d[2]), "+f"(d[3])
        : "r"(a[0]), "r"(a[1]), "r"(a[2]), "r"(a[3]), "r"(b[0]), "r"(b[1]));
}
__device__ __forceinline__ void cpasync16(uint32_t dst, const float* src){
    asm volatile("cp.async.cg.shared.global [%0], [%1], 16;"
                 :: "r"(dst), "l"(src) : "memory");
}
#define CP_COMMIT() asm volatile("cp.async.commit_group;" ::: "memory")
#define CP_WAIT1()  asm volatile("cp.async.wait_group 1;" ::: "memory")

// =================== tf32 mma.sync GEMM ====================================
// C[r,c] = sum_k A[r,k]*W[c,k] (both K-major). Tile 128x128, chunks of 32 k.
// MODE 0: +bias[c]          1: expf(acc-xd[r])/16
// MODE 2: acc/(Dv[z,r]+eps) 3: +bias[c]+addsrc[r,c]   4: plain (split-K ok)
template<int MODE>
__global__ __launch_bounds__(256, 2) void gemm_mma(
    const float* __restrict__ A, const float* __restrict__ W, float* __restrict__ C,
    int K, int ncols,
    const float* __restrict__ bias, const float* __restrict__ xd,
    const float* __restrict__ Dv, const float* __restrict__ addsrc,
    size_t aB, size_t wB, size_t cB, int dB, int splitk)
{
    extern __shared__ float sm[];
    const int tid = threadIdx.x, lane = tid & 31, wid = tid >> 5;
    const int z = blockIdx.z;
    int Keff = K;
    if (MODE == 4 && splitk > 1) {
        int b = z / splitk, sk = z - b*splitk;
        Keff = K / splitk;
        A += (size_t)b*aB + (size_t)sk*Keff;
        W += (size_t)b*wB + (size_t)sk*Keff;
        C += (size_t)z*cB;
    } else {
        A += (size_t)z*aB; W += (size_t)z*wB; C += (size_t)z*cB;
    }
    const int rowBase = blockIdx.x*128, colBase = blockIdx.y*128;

    // fill mapping: one smem row per thread (A rows 0..127, B rows 0..127)
    const int frow = tid & 127;
    const bool isB = tid >= 128;
    const float* gsrc = isB ? (W + (size_t)(colBase + frow)*K)
                            : (A + (size_t)(rowBase + frow)*K);
    const uint32_t smem_row = (uint32_t)__cvta_generic_to_shared(
        sm + (isB ? 4096 : 0) + frow*32);
    const int fsw = frow & 7;
    const int nCh = Keff / KC;

    #define LOAD_STAGE(i) do {                                           \
        if ((i) < nCh) {                                                 \
            uint32_t dstb = smem_row + ((i) % NSTAGE)*(STG_FLT*4);       \
            const float* srcb = gsrc + (i)*KC;                           \
            _Pragma("unroll")                                            \
            for (int j = 0; j < 8; j++)                                  \
                cpasync16(dstb + (uint32_t)((j ^ fsw) << 4), srcb + 4*j);\
        }                                                                \
        CP_COMMIT();                                                     \
    } while (0)

    LOAD_STAGE(0);
    LOAD_STAGE(1);

    const int wm = wid & 1, wn = wid >> 1;
    const int rq = lane >> 2, c = lane & 3;
    float acc[4][4][4];
    #pragma unroll
    for (int mi = 0; mi < 4; mi++)
        #pragma unroll
        for (int ni = 0; ni < 4; ni++)
            #pragma unroll
            for (int t = 0; t < 4; t++) acc[mi][ni][t] = 0.f;

    for (int i = 0; i < nCh; i++) {
        CP_WAIT1();
        __syncthreads();
        const float* As = sm + (i % NSTAGE)*STG_FLT;
        const float* Bs = As + 4096;
        #pragma unroll
        for (int ks = 0; ks < 4; ks++) {
            const int sw0 = (((2*ks    ) ^ rq) << 2) + c;
            const int sw1 = (((2*ks + 1) ^ rq) << 2) + c;
            uint32_t af[4][4], bf[4][2];
            #pragma unroll
            for (int mi = 0; mi < 4; mi++) {
                const float* ap = As + (wm*64 + mi*16 + rq)*32;
                af[mi][0] = f2tf(ap[sw0]);
                af[mi][1] = f2tf(ap[8*32 + sw0]);
                af[mi][2] = f2tf(ap[sw1]);
                af[mi][3] = f2tf(ap[8*32 + sw1]);
            }
            #pragma unroll
            for (int ni = 0; ni < 4; ni++) {
                const float* bp = Bs + (wn*32 + ni*8 + rq)*32;
                bf[ni][0] = f2tf(bp[sw0]);
                bf[ni][1] = f2tf(bp[sw1]);
            }
            #pragma unroll
            for (int mi = 0; mi < 4; mi++)
                #pragma unroll
                for (int ni = 0; ni < 4; ni++)
                    mma8(acc[mi][ni], af[mi], bf[ni]);
        }
        LOAD_STAGE(i + NSTAGE - 1);
    }

    // ---------------- epilogue (registers -> gmem) -------------------------
    const int c2 = c*2;
    #pragma unroll
    for (int mi = 0; mi < 4; mi++) {
        const int r0 = rowBase + wm*64 + mi*16 + rq;
        const int r1 = r0 + 8;
        float e0 = 0.f, e1 = 0.f, d0 = 1.f, d1 = 1.f;
        if (MODE == 1) { e0 = xd[r0]; e1 = xd[r1]; }
        if (MODE == 2) {
            d0 = 1.f/(Dv[(size_t)z*dB + r0] + 1e-8f);
            d1 = 1.f/(Dv[(size_t)z*dB + r1] + 1e-8f);
        }
        #pragma unroll
        for (int ni = 0; ni < 4; ni++) {
            const int cc = colBase + wn*32 + ni*8 + c2;
            float2 o0 = make_float2(acc[mi][ni][0], acc[mi][ni][1]);
            float2 o1 = make_float2(acc[mi][ni][2], acc[mi][ni][3]);
            if (MODE == 0) {
                float2 bv = *reinterpret_cast<const float2*>(bias + cc);
                o0.x += bv.x; o0.y += bv.y; o1.x += bv.x; o1.y += bv.y;
            } else if (MODE == 1) {
                o0.x = expf(o0.x - e0)*0.0625f; o0.y = expf(o0.y - e0)*0.0625f;
                o1.x = expf(o1.x - e1)*0.0625f; o1.y = expf(o1.y - e1)*0.0625f;
            } else if (MODE == 2) {
                o0.x *= d0; o0.y *= d0; o1.x *= d1; o1.y *= d1;
            } else if (MODE == 3) {
                float2 bv = *reinterpret_cast<const float2*>(bias + cc);
                float2 s0 = *reinterpret_cast<const float2*>(addsrc + (size_t)r0*ncols + cc);
                float2 s1 = *reinterpret_cast<const float2*>(addsrc + (size_t)r1*ncols + cc);
                o0.x += bv.x + s0.x; o0.y += bv.y + s0.y;
                o1.x += bv.x + s1.x; o1.y += bv.y + s1.y;
            }
            *reinterpret_cast<float2*>(C + (size_t)r0*ncols + cc) = o0;
            *reinterpret_cast<float2*>(C + (size_t)r1*ncols + cc) = o1;
        }
    }
    #undef LOAD_STAGE
}

// ---------------- LayerNorm: one block per row of 512 ---------------------
__global__ __launch_bounds__(128) void ln_kernel(
    const float* __restrict__ x, const float* __restrict__ gamma,
    const float* __restrict__ beta, float* __restrict__ out)
{
    int row = blockIdx.x;
    const float4* xr = reinterpret_cast<const float4*>(x + (size_t)row*EE);
    int t = threadIdx.x;
    float4 v = xr[t];
    float s  = v.x+v.y+v.z+v.w;
    float s2 = v.x*v.x+v.y*v.y+v.z*v.z+v.w*v.w;
    #pragma unroll
    for (int o=16;o>0;o>>=1){
        s  += __shfl_xor_sync(0xffffffffu, s,  o);
        s2 += __shfl_xor_sync(0xffffffffu, s2, o);
    }
    __shared__ float rs[4], rs2[4];
    int wid = t>>5, lane = t&31;
    if (lane==0){ rs[wid]=s; rs2[wid]=s2; }
    __syncthreads();
    s  = rs[0]+rs[1]+rs[2]+rs[3];
    s2 = rs2[0]+rs2[1]+rs2[2]+rs2[3];
    float mu  = s * (1.f/EE);
    float var = s2*(1.f/EE) - mu*mu;
    float inv = rsqrtf(var + 1e-5f);
    float4 g  = reinterpret_cast<const float4*>(gamma)[t];
    float4 bt = reinterpret_cast<const float4*>(beta)[t];
    float4 o;
    o.x = (v.x-mu)*inv*g.x + bt.x;
    o.y = (v.y-mu)*inv*g.y + bt.y;
    o.z = (v.z-mu)*inv*g.z + bt.z;
    o.w = (v.w-mu)*inv*g.w + bt.w;
    reinterpret_cast<float4*>(out + (size_t)row*EE)[t] = o;
}

// ---------------- 0.5*||row||^2 for q and k --------------------------------
__global__ __launch_bounds__(256) void xd_kernel(
    const float* __restrict__ q, const float* __restrict__ k,
    float* __restrict__ xdq, float* __restrict__ xdk)
{
    int row  = blockIdx.x*8 + (threadIdx.x>>5);
    int lane = threadIdx.x&31;
    const float4* qr = reinterpret_cast<const float4*>(q + (size_t)row*EE);
    const float4* kr = reinterpret_cast<const float4*>(k + (size_t)row*EE);
    float sq=0.f, sk=0.f;
    #pragma unroll
    for (int j=0;j<4;j++){
        float4 a = qr[lane + j*32];
        sq += a.x*a.x+a.y*a.y+a.z*a.z+a.w*a.w;
        float4 b = kr[lane + j*32];
        sk += b.x*b.x+b.y*b.y+b.z*b.z+b.w*b.w;
    }
    #pragma unroll
    for (int o=16;o>0;o>>=1){
        sq += __shfl_xor_sync(0xffffffffu, sq, o);
        sk += __shfl_xor_sync(0xffffffffu, sk, o);
    }
    if (lane==0){ xdq[row]=0.5f*sq; xdk[row]=0.5f*sk; }
}

// ---------------- column sums of kp per batch ------------------------------
__global__ __launch_bounds__(256) void ksum_kernel(
    const float* __restrict__ kp, float* __restrict__ out)
{
    int b = blockIdx.x, m0 = blockIdx.y*64;
    int tx = threadIdx.x & 63, ty = threadIdx.x >> 6;
    const float* base = kp + (size_t)b*SS*MF + m0 + tx;
    float s=0.f;
    for (int srow=ty; srow<SS; srow+=4) s += base[(size_t)srow*MF];
    __shared__ float red[4][64];
    red[ty][tx]=s;
    __syncthreads();
    if (ty==0) out[b*MF+m0+tx] = red[0][tx]+red[1][tx]+red[2][tx]+red[3][tx];
}

// ---------------- batched 2D transpose: in[z][R][Cc] -> out[z][Cc][R] ------
__global__ __launch_bounds__(256) void transpose_k(
    const float* __restrict__ in, float* __restrict__ out, int R, int Cc)
{
    __shared__ float t[32][33];
    int z = blockIdx.z;
    in  += (size_t)z*R*Cc;
    out += (size_t)z*R*Cc;
    int tx = threadIdx.x & 31, ty = threadIdx.x >> 5;  // ty in 0..7
    int x  = blockIdx.x*32 + tx;
    int y0 = blockIdx.y*32;
    #pragma unroll
    for (int j=0;j<4;j++)
        t[ty + j*8][tx] = in[(size_t)(y0 + ty + j*8)*Cc + x];
    __syncthreads();
    int xo = y0 + tx;
    int c0 = blockIdx.x*32;
    #pragma unroll
    for (int j=0;j<4;j++)
        out[(size_t)(c0 + ty + j*8)*R + xo] = t[tx][ty + j*8];
}

// ---------------- reduce split-K partials ----------------------------------
__global__ __launch_bounds__(256) void reduce_kptv(
    const float* __restrict__ p, float* __restrict__ o)
{
    const size_t EM = (size_t)EE*MF;
    size_t i = (size_t)blockIdx.x*256 + threadIdx.x;
    int b = blockIdx.y;
    const float* pb = p + (size_t)b*SPLITK*EM + i;
    float s = 0.f;
    #pragma unroll
    for (int sk=0; sk<SPLITK; sk++) s += pb[(size_t)sk*EM];
    o[(size_t)b*EM + i] = s;
}

// ---------------- D[r] = qp[r,:] . ksum[b,:] -------------------------------
__global__ __launch_bounds__(256) void d_kernel(
    const float* __restrict__ qp, const float* __restrict__ ks,
    float* __restrict__ D)
{
    int row  = blockIdx.x*8 + (threadIdx.x>>5);
    int lane = threadIdx.x&31;
    int b = row >> 12;
    const float4* qr = reinterpret_cast<const float4*>(qp + (size_t)row*MF);
    const float4* kr = reinterpret_cast<const float4*>(ks + b*MF);
    float s=0.f;
    #pragma unroll
    for (int j=0;j<2;j++){
        float4 a=qr[lane+j*32], c=kr[lane+j*32];
        s += a.x*c.x + a.y*c.y + a.z*c.z + a.w*c.w;
    }
    #pragma unroll
    for (int o=16;o>0;o>>=1) s += __shfl_xor_sync(0xffffffffu, s, o);
    if (lane==0) D[row]=s;
}

// ---------------- launch ---------------------------------------------------
extern "C" void kernel_launch(void* const* d_in, const int* in_sizes, int n_in,
                              void* d_out, int out_size)
{
    const float* x     = (const float*)d_in[0];
    const float* qw    = (const float*)d_in[1];
    const float* qb    = (const float*)d_in[2];
    const float* kw    = (const float*)d_in[3];
    const float* kb    = (const float*)d_in[4];
    const float* vw    = (const float*)d_in[5];
    const float* vb    = (const float*)d_in[6];
    const float* pw    = (const float*)d_in[7];
    const float* pb    = (const float*)d_in[8];
    const float* gamma = (const float*)d_in[9];
    const float* beta  = (const float*)d_in[10];
    const float* w     = (const float*)d_in[11];
    float* out = (float*)d_out;

    float *xn,*q,*k,*v,*y,*vt,*qp,*kp,*kpt,*xdq,*xdk,*D,*ks,*kptv,*kptvp;
    cudaGetSymbolAddress((void**)&xn,   g_xn);
    cudaGetSymbolAddress((void**)&q,    g_q);
    cudaGetSymbolAddress((void**)&k,    g_k);
    cudaGetSymbolAddress((void**)&v,    g_v);
    cudaGetSymbolAddress((void**)&y,    g_y);
    cudaGetSymbolAddress((void**)&vt,   g_vt);
    cudaGetSymbolAddress((void**)&qp,   g_qp);
    cudaGetSymbolAddress((void**)&kp,   g_kp);
    cudaGetSymbolAddress((void**)&kpt,  g_kpt);
    cudaGetSymbolAddress((void**)&xdq,  g_xdq);
    cudaGetSymbolAddress((void**)&xdk,  g_xdk);
    cudaGetSymbolAddress((void**)&D,    g_D);
    cudaGetSymbolAddress((void**)&ks,   g_ks);
    cudaGetSymbolAddress((void**)&kptv, g_kptv);
    cudaGetSymbolAddress((void**)&kptvp,g_kptvp);

    cudaFuncSetAttribute(gemm_mma<0>, cudaFuncAttributeMaxDynamicSharedMemorySize, SMEM_BYTES);
    cudaFuncSetAttribute(gemm_mma<1>, cudaFuncAttributeMaxDynamicSharedMemorySize, SMEM_BYTES);
    cudaFuncSetAttribute(gemm_mma<2>, cudaFuncAttributeMaxDynamicSharedMemorySize, SMEM_BYTES);
    cudaFuncSetAttribute(gemm_mma<3>, cudaFuncAttributeMaxDynamicSharedMemorySize, SMEM_BYTES);
    cudaFuncSetAttribute(gemm_mma<4>, cudaFuncAttributeMaxDynamicSharedMemorySize, SMEM_BYTES);

    dim3 blk(256);

    // 1) LayerNorm
    ln_kernel<<<NR,128>>>(x, gamma, beta, xn);

    // 2) q/k/v projections: [32768,512] x [512,512]^T
    dim3 gqkv(NR/128, EE/128, 1);
    gemm_mma<0><<<gqkv,blk,SMEM_BYTES>>>(xn, qw, q, EE, EE, qb, nullptr, nullptr, nullptr, 0,0,0,0,1);
    gemm_mma<0><<<gqkv,blk,SMEM_BYTES>>>(xn, kw, k, EE, EE, kb, nullptr, nullptr, nullptr, 0,0,0,0,1);
    gemm_mma<0><<<gqkv,blk,SMEM_BYTES>>>(xn, vw, v, EE, EE, vb, nullptr, nullptr, nullptr, 0,0,0,0,1);

    // 3) row half-norms
    xd_kernel<<<NR/8,256>>>(q, k, xdq, xdk);

    // 4) qp/kp random features (exp epilogue)
    dim3 gqp(NR/128, MF/128, 1);
    gemm_mma<1><<<gqp,blk,SMEM_BYTES>>>(q, w, qp, EE, MF, nullptr, xdq, nullptr, nullptr, 0,0,0,0,1);
    gemm_mma<1><<<gqp,blk,SMEM_BYTES>>>(k, w, kp, EE, MF, nullptr, xdk, nullptr, nullptr, 0,0,0,0,1);

    // 5) ksum[b,m]
    ksum_kernel<<<dim3(BB, MF/64),blk>>>(kp, ks);

    // 6) transposes: vt[b][E][S], kpt[b][M][S]
    transpose_k<<<dim3(EE/32, SS/32, BB),blk>>>(v,  vt,  SS, EE);
    transpose_k<<<dim3(MF/32, SS/32, BB),blk>>>(kp, kpt, SS, MF);

    // 7) kptv[b,e,m] = sum_s vt[b,e,s]*kpt[b,m,s], split-K=8, then reduce
    gemm_mma<4><<<dim3(EE/128, MF/128, BB*SPLITK),blk,SMEM_BYTES>>>(
        vt, kpt, kptvp, SS, MF, nullptr, nullptr, nullptr, nullptr,
        (size_t)EE*SS, (size_t)MF*SS, (size_t)EE*MF, 0, SPLITK);
    reduce_kptv<<<dim3((EE*MF)/256, BB),blk>>>(kptvp, kptv);

    // 8) D[r]
    d_kernel<<<NR/8,256>>>(qp, ks, D);

    // 9) y[b,s,e] = (qp @ kptv^T) / (D + eps)   (per-batch, K=256)
    gemm_mma<2><<<dim3(SS/128, EE/128, BB),blk,SMEM_BYTES>>>(
        qp, kptv, y, MF, EE, nullptr, nullptr, D, nullptr,
        (size_t)SS*MF, (size_t)EE*MF, (size_t)SS*EE, SS, 1);

    // 10) out = v + y @ pw^T + pb
    gemm_mma<3><<<gqkv,blk,SMEM_BYTES>>>(y, pw, out, EE, EE, pb, nullptr, nullptr, v, 0,0,0,0,1);
}

// round 6
// speedup vs baseline: 1.9661x; 1.0003x over previous
#include <cuda_runtime.h>
#include <math.h>
#include <stdint.h>

#define BB 8
#define SS 4096
#define NR (BB*SS)      // 32768 rows
#define EE 512
#define MF 256
#define SPLITK 8
#define NSTAGE 3
#define KC 32                       // k floats per chunk
#define STG_FLT 8192                // floats per stage: A 128*32 + B 128*32
#define SMEM_BYTES (NSTAGE*STG_FLT*4)

// ---------------- scratch (device globals; no allocation allowed) ----------
__device__ float g_xn [(size_t)NR*EE];
__device__ float g_q  [(size_t)NR*EE];
__device__ float g_k  [(size_t)NR*EE];
__device__ float g_v  [(size_t)NR*EE];
__device__ float g_y  [(size_t)NR*EE];
__device__ float g_vt [(size_t)NR*EE];   // [b][E][S]
__device__ float g_qp [(size_t)NR*MF];
__device__ float g_kp [(size_t)NR*MF];
__device__ float g_kpt[(size_t)NR*MF];   // [b][M][S]
__device__ float g_xdq[NR];
__device__ float g_xdk[NR];
__device__ float g_D  [NR];
__device__ float g_ks [BB*MF];
__device__ float g_kptv [(size_t)BB*EE*MF];
__device__ float g_kptvp[(size_t)SPLITK*BB*EE*MF];

// =================== portable tensor-core helpers (sm_80+) =================
__device__ __forceinline__ uint32_t f2tf(float f){
    uint32_t r; asm("cvt.rna.tf32.f32 %0, %1;" : "=r"(r) : "f"(f)); return r;
}
__device__ __forceinline__ void mma8(float* d, const uint32_t* a, const uint32_t* b){
    asm volatile("mma.sync.aligned.m16n8k8.row.col.f32.tf32.tf32.f32 "
        "{%0,%1,%2,%3}, {%4,%5,%6,%7}, {%8,%9}, {%0,%1,%2,%3};"
        : "+f"(d[0]), "+f"(d[1]), "+f"(d[2]), "+f"(d[3])
        : "r"(a[0]), "r"(a[1]), "r"(a[2]), "r"(a[3]), "r"(b[0]), "r"(b[1]));
}
__device__ __forceinline__ void cpasync16(uint32_t dst, const float* src){
    asm volatile("cp.async.cg.shared.global [%0], [%1], 16;"
                 :: "r"(dst), "l"(src) : "memory");
}
#define CP_COMMIT() asm volatile("cp.async.commit_group;" ::: "memory")
#define CP_WAIT1()  asm volatile("cp.async.wait_group 1;" ::: "memory")

// =================== tf32 mma.sync GEMM ====================================
// C[r,c] = sum_k A[r,k]*W[c,k] (both K-major). Tile 128x128, chunks of 32 k.
// MODE 0: +bias[c]          1: expf(acc-xd[r])/16
// MODE 2: acc/(Dv[z,r]+eps) 3: +bias[c]+addsrc[r,c]   4: plain (split-K ok)
template<int MODE>
__global__ __launch_bounds__(256, 2) void gemm_mma(
    const float* __restrict__ A, const float* __restrict__ W, float* __restrict__ C,
    int K, int ncols,
    const float* __restrict__ bias, const float* __restrict__ xd,
    const float* __restrict__ Dv, const float* __restrict__ addsrc,
    size_t aB, size_t wB, size_t cB, int dB, int splitk)
{
    extern __shared__ float sm[];
    const int tid = threadIdx.x, lane = tid & 31, wid = tid >> 5;
    const int z = blockIdx.z;
    int Keff = K;
    if (MODE == 4 && splitk > 1) {
        int b = z / splitk, sk = z - b*splitk;
        Keff = K / splitk;
        A += (size_t)b*aB + (size_t)sk*Keff;
        W += (size_t)b*wB + (size_t)sk*Keff;
        C += (size_t)z*cB;
    } else {
        A += (size_t)z*aB; W += (size_t)z*wB; C += (size_t)z*cB;
    }
    const int rowBase = blockIdx.x*128, colBase = blockIdx.y*128;

    // fill mapping: one smem row per thread (A rows 0..127, B rows 0..127)
    const int frow = tid & 127;
    const bool isB = tid >= 128;
    const float* gsrc = isB ? (W + (size_t)(colBase + frow)*K)
                            : (A + (size_t)(rowBase + frow)*K);
    const uint32_t smem_row = (uint32_t)__cvta_generic_to_shared(
        sm + (isB ? 4096 : 0) + frow*32);
    const int fsw = frow & 7;
    const int nCh = Keff / KC;

    #define LOAD_STAGE(i) do {                                           \
        if ((i) < nCh) {                                                 \
            uint32_t dstb = smem_row + ((i) % NSTAGE)*(STG_FLT*4);       \
            const float* srcb = gsrc + (i)*KC;                           \
            _Pragma("unroll")                                            \
            for (int j = 0; j < 8; j++)                                  \
                cpasync16(dstb + (uint32_t)((j ^ fsw) << 4), srcb + 4*j);\
        }                                                                \
        CP_COMMIT();                                                     \
    } while (0)

    LOAD_STAGE(0);
    LOAD_STAGE(1);

    const int wm = wid & 1, wn = wid >> 1;
    const int rq = lane >> 2, c = lane & 3;
    float acc[4][4][4];
    #pragma unroll
    for (int mi = 0; mi < 4; mi++)
        #pragma unroll
        for (int ni = 0; ni < 4; ni++)
            #pragma unroll
            for (int t = 0; t < 4; t++) acc[mi][ni][t] = 0.f;

    for (int i = 0; i < nCh; i++) {
        CP_WAIT1();
        __syncthreads();
        const float* As = sm + (i % NSTAGE)*STG_FLT;
        const float* Bs = As + 4096;
        #pragma unroll
        for (int ks = 0; ks < 4; ks++) {
            const int sw0 = (((2*ks    ) ^ rq) << 2) + c;
            const int sw1 = (((2*ks + 1) ^ rq) << 2) + c;
            uint32_t af[4][4], bf[4][2];
            #pragma unroll
            for (int mi = 0; mi < 4; mi++) {
                const float* ap = As + (wm*64 + mi*16 + rq)*32;
                af[mi][0] = f2tf(ap[sw0]);
                af[mi][1] = f2tf(ap[8*32 + sw0]);
                af[mi][2] = f2tf(ap[sw1]);
                af[mi][3] = f2tf(ap[8*32 + sw1]);
            }
            #pragma unroll
            for (int ni = 0; ni < 4; ni++) {
                const float* bp = Bs + (wn*32 + ni*8 + rq)*32;
                bf[ni][0] = f2tf(bp[sw0]);
                bf[ni][1] = f2tf(bp[sw1]);
            }
            #pragma unroll
            for (int mi = 0; mi < 4; mi++)
                #pragma unroll
                for (int ni = 0; ni < 4; ni++)
                    mma8(acc[mi][ni], af[mi], bf[ni]);
        }
        LOAD_STAGE(i + NSTAGE - 1);
    }

    // ---------------- epilogue (registers -> gmem) -------------------------
    const int c2 = c*2;
    #pragma unroll
    for (int mi = 0; mi < 4; mi++) {
        const int r0 = rowBase + wm*64 + mi*16 + rq;
        const int r1 = r0 + 8;
        float e0 = 0.f, e1 = 0.f, d0 = 1.f, d1 = 1.f;
        if (MODE == 1) { e0 = xd[r0]; e1 = xd[r1]; }
        if (MODE == 2) {
            d0 = 1.f/(Dv[(size_t)z*dB + r0] + 1e-8f);
            d1 = 1.f/(Dv[(size_t)z*dB + r1] + 1e-8f);
        }
        #pragma unroll
        for (int ni = 0; ni < 4; ni++) {
            const int cc = colBase + wn*32 + ni*8 + c2;
            float2 o0 = make_float2(acc[mi][ni][0], acc[mi][ni][1]);
            float2 o1 = make_float2(acc[mi][ni][2], acc[mi][ni][3]);
            if (MODE == 0) {
                float2 bv = *reinterpret_cast<const float2*>(bias + cc);
                o0.x += bv.x; o0.y += bv.y; o1.x += bv.x; o1.y += bv.y;
            } else if (MODE == 1) {
                o0.x = expf(o0.x - e0)*0.0625f; o0.y = expf(o0.y - e0)*0.0625f;
                o1.x = expf(o1.x - e1)*0.0625f; o1.y = expf(o1.y - e1)*0.0625f;
            } else if (MODE == 2) {
                o0.x *= d0; o0.y *= d0; o1.x *= d1; o1.y *= d1;
            } else if (MODE == 3) {
                float2 bv = *reinterpret_cast<const float2*>(bias + cc);
                float2 s0 = *reinterpret_cast<const float2*>(addsrc + (size_t)r0*ncols + cc);
                float2 s1 = *reinterpret_cast<const float2*>(addsrc + (size_t)r1*ncols + cc);
                o0.x += bv.x + s0.x; o0.y += bv.y + s0.y;
                o1.x += bv.x + s1.x; o1.y += bv.y + s1.y;
            }
            *reinterpret_cast<float2*>(C + (size_t)r0*ncols + cc) = o0;
            *reinterpret_cast<float2*>(C + (size_t)r1*ncols + cc) = o1;
        }
    }
    #undef LOAD_STAGE
}

// ---------------- LayerNorm: one block per row of 512 ---------------------
__global__ __launch_bounds__(128) void ln_kernel(
    const float* __restrict__ x, const float* __restrict__ gamma,
    const float* __restrict__ beta, float* __restrict__ out)
{
    int row = blockIdx.x;
    const float4* xr = reinterpret_cast<const float4*>(x + (size_t)row*EE);
    int t = threadIdx.x;
    float4 v = xr[t];
    float s  = v.x+v.y+v.z+v.w;
    float s2 = v.x*v.x+v.y*v.y+v.z*v.z+v.w*v.w;
    #pragma unroll
    for (int o=16;o>0;o>>=1){
        s  += __shfl_xor_sync(0xffffffffu, s,  o);
        s2 += __shfl_xor_sync(0xffffffffu, s2, o);
    }
    __shared__ float rs[4], rs2[4];
    int wid = t>>5, lane = t&31;
    if (lane==0){ rs[wid]=s; rs2[wid]=s2; }
    __syncthreads();
    s  = rs[0]+rs[1]+rs[2]+rs[3];
    s2 = rs2[0]+rs2[1]+rs2[2]+rs2[3];
    float mu  = s * (1.f/EE);
    float var = s2*(1.f/EE) - mu*mu;
    float inv = rsqrtf(var + 1e-5f);
    float4 g  = reinterpret_cast<const float4*>(gamma)[t];
    float4 bt = reinterpret_cast<const float4*>(beta)[t];
    float4 o;
    o.x = (v.x-mu)*inv*g.x + bt.x;
    o.y = (v.y-mu)*inv*g.y + bt.y;
    o.z = (v.z-mu)*inv*g.z + bt.z;
    o.w = (v.w-mu)*inv*g.w + bt.w;
    reinterpret_cast<float4*>(out + (size_t)row*EE)[t] = o;
}

// ---------------- 0.5*||row||^2 for q and k --------------------------------
__global__ __launch_bounds__(256) void xd_kernel(
    const float* __restrict__ q, const float* __restrict__ k,
    float* __restrict__ xdq, float* __restrict__ xdk)
{
    int row  = blockIdx.x*8 + (threadIdx.x>>5);
    int lane = threadIdx.x&31;
    const float4* qr = reinterpret_cast<const float4*>(q + (size_t)row*EE);
    const float4* kr = reinterpret_cast<const float4*>(k + (size_t)row*EE);
    float sq=0.f, sk=0.f;
    #pragma unroll
    for (int j=0;j<4;j++){
        float4 a = qr[lane + j*32];
        sq += a.x*a.x+a.y*a.y+a.z*a.z+a.w*a.w;
        float4 b = kr[lane + j*32];
        sk += b.x*b.x+b.y*b.y+b.z*b.z+b.w*b.w;
    }
    #pragma unroll
    for (int o=16;o>0;o>>=1){
        sq += __shfl_xor_sync(0xffffffffu, sq, o);
        sk += __shfl_xor_sync(0xffffffffu, sk, o);
    }
    if (lane==0){ xdq[row]=0.5f*sq; xdk[row]=0.5f*sk; }
}

// ---------------- column sums of kp per batch ------------------------------
__global__ __launch_bounds__(256) void ksum_kernel(
    const float* __restrict__ kp, float* __restrict__ out)
{
    int b = blockIdx.x, m0 = blockIdx.y*64;
    int tx = threadIdx.x & 63, ty = threadIdx.x >> 6;
    const float* base = kp + (size_t)b*SS*MF + m0 + tx;
    float s=0.f;
    for (int srow=ty; srow<SS; srow+=4) s += base[(size_t)srow*MF];
    __shared__ float red[4][64];
    red[ty][tx]=s;
    __syncthreads();
    if (ty==0) out[b*MF+m0+tx] = red[0][tx]+red[1][tx]+red[2][tx]+red[3][tx];
}

// ---------------- batched 2D transpose: in[z][R][Cc] -> out[z][Cc][R] ------
__global__ __launch_bounds__(256) void transpose_k(
    const float* __restrict__ in, float* __restrict__ out, int R, int Cc)
{
    __shared__ float t[32][33];
    int z = blockIdx.z;
    in  += (size_t)z*R*Cc;
    out += (size_t)z*R*Cc;
    int tx = threadIdx.x & 31, ty = threadIdx.x >> 5;  // ty in 0..7
    int x  = blockIdx.x*32 + tx;
    int y0 = blockIdx.y*32;
    #pragma unroll
    for (int j=0;j<4;j++)
        t[ty + j*8][tx] = in[(size_t)(y0 + ty + j*8)*Cc + x];
    __syncthreads();
    int xo = y0 + tx;
    int c0 = blockIdx.x*32;
    #pragma unroll
    for (int j=0;j<4;j++)
        out[(size_t)(c0 + ty + j*8)*R + xo] = t[tx][ty + j*8];
}

// ---------------- reduce split-K partials ----------------------------------
__global__ __launch_bounds__(256) void reduce_kptv(
    const float* __restrict__ p, float* __restrict__ o)
{
    const size_t EM = (size_t)EE*MF;
    size_t i = (size_t)blockIdx.x*256 + threadIdx.x;
    int b = blockIdx.y;
    const float* pb = p + (size_t)b*SPLITK*EM + i;
    float s = 0.f;
    #pragma unroll
    for (int sk=0; sk<SPLITK; sk++) s += pb[(size_t)sk*EM];
    o[(size_t)b*EM + i] = s;
}

// ---------------- D[r] = qp[r,:] . ksum[b,:] -------------------------------
__global__ __launch_bounds__(256) void d_kernel(
    const float* __restrict__ qp, const float* __restrict__ ks,
    float* __restrict__ D)
{
    int row  = blockIdx.x*8 + (threadIdx.x>>5);
    int lane = threadIdx.x&31;
    int b = row >> 12;
    const float4* qr = reinterpret_cast<const float4*>(qp + (size_t)row*MF);
    const float4* kr = reinterpret_cast<const float4*>(ks + b*MF);
    float s=0.f;
    #pragma unroll
    for (int j=0;j<2;j++){
        float4 a=qr[lane+j*32], c=kr[lane+j*32];
        s += a.x*c.x + a.y*c.y + a.z*c.z + a.w*c.w;
    }
    #pragma unroll
    for (int o=16;o>0;o>>=1) s += __shfl_xor_sync(0xffffffffu, s, o);
    if (lane==0) D[row]=s;
}

// ---------------- launch ---------------------------------------------------
extern "C" void kernel_launch(void* const* d_in, const int* in_sizes, int n_in,
                              void* d_out, int out_size)
{
    const float* x     = (const float*)d_in[0];
    const float* qw    = (const float*)d_in[1];
    const float* qb    = (const float*)d_in[2];
    const float* kw    = (const float*)d_in[3];
    const float* kb    = (const float*)d_in[4];
    const float* vw    = (const float*)d_in[5];
    const float* vb    = (const float*)d_in[6];
    const float* pw    = (const float*)d_in[7];
    const float* pb    = (const float*)d_in[8];
    const float* gamma = (const float*)d_in[9];
    const float* beta  = (const float*)d_in[10];
    const float* w     = (const float*)d_in[11];
    float* out = (float*)d_out;

    float *xn,*q,*k,*v,*y,*vt,*qp,*kp,*kpt,*xdq,*xdk,*D,*ks,*kptv,*kptvp;
    cudaGetSymbolAddress((void**)&xn,   g_xn);
    cudaGetSymbolAddress((void**)&q,    g_q);
    cudaGetSymbolAddress((void**)&k,    g_k);
    cudaGetSymbolAddress((void**)&v,    g_v);
    cudaGetSymbolAddress((void**)&y,    g_y);
    cudaGetSymbolAddress((void**)&vt,   g_vt);
    cudaGetSymbolAddress((void**)&qp,   g_qp);
    cudaGetSymbolAddress((void**)&kp,   g_kp);
    cudaGetSymbolAddress((void**)&kpt,  g_kpt);
    cudaGetSymbolAddress((void**)&xdq,  g_xdq);
    cudaGetSymbolAddress((void**)&xdk,  g_xdk);
    cudaGetSymbolAddress((void**)&D,    g_D);
    cudaGetSymbolAddress((void**)&ks,   g_ks);
    cudaGetSymbolAddress((void**)&kptv, g_kptv);
    cudaGetSymbolAddress((void**)&kptvp,g_kptvp);

    cudaFuncSetAttribute(gemm_mma<0>, cudaFuncAttributeMaxDynamicSharedMemorySize, SMEM_BYTES);
    cudaFuncSetAttribute(gemm_mma<1>, cudaFuncAttributeMaxDynamicSharedMemorySize, SMEM_BYTES);
    cudaFuncSetAttribute(gemm_mma<2>, cudaFuncAttributeMaxDynamicSharedMemorySize, SMEM_BYTES);
    cudaFuncSetAttribute(gemm_mma<3>, cudaFuncAttributeMaxDynamicSharedMemorySize, SMEM_BYTES);
    cudaFuncSetAttribute(gemm_mma<4>, cudaFuncAttributeMaxDynamicSharedMemorySize, SMEM_BYTES);

    dim3 blk(256);

    // 1) LayerNorm
    ln_kernel<<<NR,128>>>(x, gamma, beta, xn);

    // 2) q/k/v projections: [32768,512] x [512,512]^T
    dim3 gqkv(NR/128, EE/128, 1);
    gemm_mma<0><<<gqkv,blk,SMEM_BYTES>>>(xn, qw, q, EE, EE, qb, nullptr, nullptr, nullptr, 0,0,0,0,1);
    gemm_mma<0><<<gqkv,blk,SMEM_BYTES>>>(xn, kw, k, EE, EE, kb, nullptr, nullptr, nullptr, 0,0,0,0,1);
    gemm_mma<0><<<gqkv,blk,SMEM_BYTES>>>(xn, vw, v, EE, EE, vb, nullptr, nullptr, nullptr, 0,0,0,0,1);

    // 3) row half-norms
    xd_kernel<<<NR/8,256>>>(q, k, xdq, xdk);

    // 4) qp/kp random features (exp epilogue)
    dim3 gqp(NR/128, MF/128, 1);
    gemm_mma<1><<<gqp,blk,SMEM_BYTES>>>(q, w, qp, EE, MF, nullptr, xdq, nullptr, nullptr, 0,0,0,0,1);
    gemm_mma<1><<<gqp,blk,SMEM_BYTES>>>(k, w, kp, EE, MF, nullptr, xdk, nullptr, nullptr, 0,0,0,0,1);

    // 5) ksum[b,m]
    ksum_kernel<<<dim3(BB, MF/64),blk>>>(kp, ks);

    // 6) transposes: vt[b][E][S], kpt[b][M][S]
    transpose_k<<<dim3(EE/32, SS/32, BB),blk>>>(v,  vt,  SS, EE);
    transpose_k<<<dim3(MF/32, SS/32, BB),blk>>>(kp, kpt, SS, MF);

    // 7) kptv[b,e,m] = sum_s vt[b,e,s]*kpt[b,m,s], split-K=8, then reduce
    gemm_mma<4><<<dim3(EE/128, MF/128, BB*SPLITK),blk,SMEM_BYTES>>>(
        vt, kpt, kptvp, SS, MF, nullptr, nullptr, nullptr, nullptr,
        (size_t)EE*SS, (size_t)MF*SS, (size_t)EE*MF, 0, SPLITK);
    reduce_kptv<<<dim3((EE*MF)/256, BB),blk>>>(kptvp, kptv);

    // 8) D[r]
    d_kernel<<<NR/8,256>>>(qp, ks, D);

    // 9) y[b,s,e] = (qp @ kptv^T) / (D + eps)   (per-batch, K=256)
    gemm_mma<2><<<dim3(SS/128, EE/128, BB),blk,SMEM_BYTES>>>(
        qp, kptv, y, MF, EE, nullptr, nullptr, D, nullptr,
        (size_t)SS*MF, (size_t)EE*MF, (size_t)SS*EE, SS, 1);

    // 10) out = v + y @ pw^T + pb
    gemm_mma<3><<<gqkv,blk,SMEM_BYTES>>>(y, pw, out, EE, EE, pb, nullptr, nullptr, v, 0,0,0,0,1);
}

// round 7
// speedup vs baseline: 2.8140x; 1.4312x over previous
#include <cuda_runtime.h>
#include <cuda_bf16.h>
#include <math.h>
#include <stdint.h>

#define BB 8
#define SS 4096
#define NR (BB*SS)      // 32768 rows
#define EE 512
#define MF 256
#define SPLITK 8
#define NSTAGE 3
#define KCB 64                      // k elements (bf16) per chunk = 128B rows
#define STG_B 32768                 // bytes per stage: A 16KB + B 16KB
#define SMEM_B (NSTAGE*STG_B)       // 96KB

typedef __nv_bfloat16 bf16;
typedef __nv_bfloat162 bf162;

// ---------------- scratch (device globals; no allocation allowed) ----------
__device__ bf16  g_xnh [(size_t)NR*EE];
__device__ bf16  g_xnl [(size_t)NR*EE];
__device__ bf16  g_qb  [(size_t)NR*EE];
__device__ bf16  g_kb  [(size_t)NR*EE];
__device__ bf16  g_yb  [(size_t)NR*EE];
__device__ bf16  g_vtb [(size_t)NR*EE];    // [b][E][S]
__device__ bf16  g_qpb [(size_t)NR*MF];
__device__ bf16  g_kpb [(size_t)NR*MF];
__device__ bf16  g_kptb[(size_t)NR*MF];    // [b][M][S]
__device__ float g_v   [(size_t)NR*EE];
__device__ float g_t1  [(size_t)NR*EE];
__device__ float g_xdq[NR];
__device__ float g_xdk[NR];
__device__ float g_D  [NR];
__device__ float g_ks [BB*MF];
__device__ float g_kptvp[(size_t)SPLITK*BB*EE*MF];
__device__ bf16  g_kptvb[(size_t)BB*EE*MF];
__device__ bf16  g_qwb[EE*EE];
__device__ bf16  g_kwb[EE*EE];
__device__ bf16  g_pwb[EE*EE];
__device__ bf16  g_wb [MF*EE];
__device__ bf16  g_vwh[EE*EE];
__device__ bf16  g_vwl[EE*EE];

// =================== portable tensor-core helpers (sm_75/80+) ==============
__device__ __forceinline__ void ldsm4(uint32_t* r, uint32_t addr){
    asm volatile("ldmatrix.sync.aligned.m8n8.x4.shared.b16 {%0,%1,%2,%3}, [%4];"
        : "=r"(r[0]), "=r"(r[1]), "=r"(r[2]), "=r"(r[3]) : "r"(addr));
}
__device__ __forceinline__ void mma16(float* d, const uint32_t* a, const uint32_t* b){
    asm volatile("mma.sync.aligned.m16n8k16.row.col.f32.bf16.bf16.f32 "
        "{%0,%1,%2,%3}, {%4,%5,%6,%7}, {%8,%9}, {%0,%1,%2,%3};"
        : "+f"(d[0]), "+f"(d[1]), "+f"(d[2]), "+f"(d[3])
        : "r"(a[0]), "r"(a[1]), "r"(a[2]), "r"(a[3]), "r"(b[0]), "r"(b[1]));
}
__device__ __forceinline__ void cpa16(uint32_t dst, const void* src){
    asm volatile("cp.async.cg.shared.global [%0], [%1], 16;"
                 :: "r"(dst), "l"(src) : "memory");
}
#define CP_COMMIT() asm volatile("cp.async.commit_group;" ::: "memory")
#define CP_WAIT1()  asm volatile("cp.async.wait_group 1;" ::: "memory")

// =================== bf16 mma.sync GEMM ====================================
// C[r,c] = sum_k A[r,k]*W[c,k], A/W bf16 K-major (row strides lda/ldw elements)
// Tile 128x128 (8 warps 2m x 4n, warp 64x32), K chunks of 64, fp32 accum.
// MODE 0: +bias[c]            -> bf16 out   (q/k proj)
// MODE 1: expf(acc-xd[r])/16  -> bf16 out   (features)
// MODE 2: acc/(Dv[z,r]+eps)   -> bf16 out   (y)
// MODE 3: +bias[c]+addsrc     -> f32 out    (v main, final)
// MODE 4: plain               -> f32 out    (kptv partials / t1; split-K ok)
// MODE 5: +addsrc             -> f32 out    (t1 += xnl@vwh; addsrc may ==C)
template<int MODE>
__global__ __launch_bounds__(256, 2) void gemm_bf(
    const bf16* __restrict__ A, const bf16* __restrict__ W, void* __restrict__ Cv,
    int K, int lda, int ldw, int ncols,
    const float* __restrict__ bias, const float* __restrict__ xd,
    const float* __restrict__ Dv, const float* __restrict__ addsrc,
    size_t aB, size_t wB, size_t cB, int dB, int splitk)
{
    extern __shared__ char smc[];
    const uint32_t sb = (uint32_t)__cvta_generic_to_shared(smc);
    const int tid = threadIdx.x, lane = tid & 31, wid = tid >> 5;
    const int z = blockIdx.z;
    const bf16* Ab = A;
    const bf16* Wb = W;
    size_t cOff;
    if (MODE == 4 && splitk > 1) {
        int b = z / splitk, sk = z - b*splitk;
        Ab += b*aB + (size_t)sk*K;
        Wb += b*wB + (size_t)sk*K;
        cOff = (size_t)z*cB;
    } else {
        Ab += (size_t)z*aB; Wb += (size_t)z*wB; cOff = (size_t)z*cB;
    }
    const int rowBase = blockIdx.x*128, colBase = blockIdx.y*128;

    // fill mapping: one 128B smem row per thread
    const int frow = tid & 127;
    const bool isB = tid >= 128;
    const bf16* gsrc = isB ? (Wb + (size_t)(colBase + frow)*ldw)
                           : (Ab + (size_t)(rowBase + frow)*lda);
    const uint32_t srow = sb + (isB ? 16384u : 0u) + (uint32_t)frow*128u;
    const int fsw = frow & 7;
    const int nCh = K / KCB;

    #define LOAD_STAGE(i) do {                                            \
        if ((i) < nCh) {                                                  \
            uint32_t dstb = srow + ((i) % NSTAGE)*STG_B;                  \
            const bf16* srcb = gsrc + (size_t)(i)*KCB;                    \
            _Pragma("unroll")                                             \
            for (int j = 0; j < 8; j++)                                   \
                cpa16(dstb + (uint32_t)((j ^ fsw) << 4), srcb + 8*j);     \
        }                                                                 \
        CP_COMMIT();                                                      \
    } while (0)

    LOAD_STAGE(0);
    LOAD_STAGE(1);

    const int wm = wid & 1, wn = wid >> 1;
    const int rq = lane >> 2;
    const int sw = lane & 7;                       // swizzle key for ldmatrix rows
    const int lrow8 = (lane & 7) + ((lane >> 3) & 1) * 8;
    const int khalf = lane >> 4;                   // 16B half within k16
    uint32_t aOff[4], bOff[2];
    #pragma unroll
    for (int mi = 0; mi < 4; mi++)
        aOff[mi] = (uint32_t)(wm*64 + mi*16 + lrow8) * 128u;
    #pragma unroll
    for (int nb = 0; nb < 2; nb++)
        bOff[nb] = (uint32_t)(wn*32 + nb*16 + lrow8) * 128u + 16384u;

    float acc[4][4][4];
    #pragma unroll
    for (int mi = 0; mi < 4; mi++)
        #pragma unroll
        for (int ni = 0; ni < 4; ni++)
            #pragma unroll
            for (int t = 0; t < 4; t++) acc[mi][ni][t] = 0.f;

    for (int i = 0; i < nCh; i++) {
        CP_WAIT1();
        __syncthreads();
        const uint32_t sA = sb + (i % NSTAGE)*STG_B;
        #pragma unroll
        for (int ks = 0; ks < 4; ks++) {
            const uint32_t kq = (uint32_t)(((ks*2 + khalf) ^ sw) << 4);
            uint32_t af[4][4], bfr[4][2];
            #pragma unroll
            for (int mi = 0; mi < 4; mi++)
                ldsm4(af[mi], sA + aOff[mi] + kq);
            #pragma unroll
            for (int nb = 0; nb < 2; nb++) {
                uint32_t m[4];
                ldsm4(m, sA + bOff[nb] + kq);
                bfr[2*nb  ][0] = m[0]; bfr[2*nb+1][0] = m[1];
                bfr[2*nb  ][1] = m[2]; bfr[2*nb+1][1] = m[3];
            }
            #pragma unroll
            for (int mi = 0; mi < 4; mi++)
                #pragma unroll
                for (int ni = 0; ni < 4; ni++)
                    mma16(acc[mi][ni], af[mi], bfr[ni]);
        }
        LOAD_STAGE(i + NSTAGE - 1);
    }

    // ---------------- epilogue ---------------------------------------------
    bf16*  Cb = (bf16*)Cv + cOff;
    float* Cf = (float*)Cv + cOff;
    const int c2 = (lane & 3)*2;
    #pragma unroll
    for (int mi = 0; mi < 4; mi++) {
        const int r0 = rowBase + wm*64 + mi*16 + rq;
        const int r1 = r0 + 8;
        float e0 = 0.f, e1 = 0.f, d0 = 1.f, d1 = 1.f;
        if (MODE == 1) { e0 = xd[r0]; e1 = xd[r1]; }
        if (MODE == 2) {
            d0 = 1.f/(Dv[(size_t)z*dB + r0] + 1e-8f);
            d1 = 1.f/(Dv[(size_t)z*dB + r1] + 1e-8f);
        }
        #pragma unroll
        for (int ni = 0; ni < 4; ni++) {
            const int cc = colBase + wn*32 + ni*8 + c2;
            float t0 = acc[mi][ni][0], t1v = acc[mi][ni][1];
            float t2 = acc[mi][ni][2], t3  = acc[mi][ni][3];
            if (MODE == 0) {
                float2 bv = *reinterpret_cast<const float2*>(bias + cc);
                t0 += bv.x; t1v += bv.y; t2 += bv.x; t3 += bv.y;
            } else if (MODE == 1) {
                t0 = expf(t0 - e0)*0.0625f; t1v = expf(t1v - e0)*0.0625f;
                t2 = expf(t2 - e1)*0.0625f; t3  = expf(t3  - e1)*0.0625f;
            } else if (MODE == 2) {
                t0 *= d0; t1v *= d0; t2 *= d1; t3 *= d1;
            } else if (MODE == 3) {
                float2 bv = *reinterpret_cast<const float2*>(bias + cc);
                float2 s0 = *reinterpret_cast<const float2*>(addsrc + (size_t)r0*ncols + cc);
                float2 s1 = *reinterpret_cast<const float2*>(addsrc + (size_t)r1*ncols + cc);
                t0 += bv.x + s0.x; t1v += bv.y + s0.y;
                t2 += bv.x + s1.x; t3  += bv.y + s1.y;
            } else if (MODE == 5) {
                float2 s0 = *reinterpret_cast<const float2*>(addsrc + (size_t)r0*ncols + cc);
                float2 s1 = *reinterpret_cast<const float2*>(addsrc + (size_t)r1*ncols + cc);
                t0 += s0.x; t1v += s0.y; t2 += s1.x; t3 += s1.y;
            }
            if (MODE <= 2) {
                *reinterpret_cast<bf162*>(Cb + (size_t)r0*ncols + cc) = __floats2bfloat162_rn(t0, t1v);
                *reinterpret_cast<bf162*>(Cb + (size_t)r1*ncols + cc) = __floats2bfloat162_rn(t2, t3);
            } else {
                *reinterpret_cast<float2*>(Cf + (size_t)r0*ncols + cc) = make_float2(t0, t1v);
                *reinterpret_cast<float2*>(Cf + (size_t)r1*ncols + cc) = make_float2(t2, t3);
            }
        }
    }
    #undef LOAD_STAGE
}

// ---------------- conversions ----------------------------------------------
__global__ __launch_bounds__(256) void conv_b(const float* __restrict__ s,
                                              bf16* __restrict__ d, int n){
    int i = blockIdx.x*256 + threadIdx.x;
    if (i < n) d[i] = __float2bfloat16_rn(s[i]);
}
__global__ __launch_bounds__(256) void conv_split(const float* __restrict__ s,
    bf16* __restrict__ h, bf16* __restrict__ l, int n){
    int i = blockIdx.x*256 + threadIdx.x;
    if (i < n) {
        float v = s[i];
        bf16 hv = __float2bfloat16_rn(v);
        h[i] = hv;
        l[i] = __float2bfloat16_rn(v - __bfloat162float(hv));
    }
}

// ---------------- LayerNorm -> (hi, lo) bf16 -------------------------------
__global__ __launch_bounds__(128) void ln_kernel(
    const float* __restrict__ x, const float* __restrict__ gamma,
    const float* __restrict__ beta, bf16* __restrict__ xh, bf16* __restrict__ xl)
{
    int row = blockIdx.x;
    const float4* xr = reinterpret_cast<const float4*>(x + (size_t)row*EE);
    int t = threadIdx.x;
    float4 v = xr[t];
    float s  = v.x+v.y+v.z+v.w;
    float s2 = v.x*v.x+v.y*v.y+v.z*v.z+v.w*v.w;
    #pragma unroll
    for (int o=16;o>0;o>>=1){
        s  += __shfl_xor_sync(0xffffffffu, s,  o);
        s2 += __shfl_xor_sync(0xffffffffu, s2, o);
    }
    __shared__ float rs[4], rs2[4];
    int wid = t>>5, lane = t&31;
    if (lane==0){ rs[wid]=s; rs2[wid]=s2; }
    __syncthreads();
    s  = rs[0]+rs[1]+rs[2]+rs[3];
    s2 = rs2[0]+rs2[1]+rs2[2]+rs2[3];
    float mu  = s * (1.f/EE);
    float var = s2*(1.f/EE) - mu*mu;
    float inv = rsqrtf(var + 1e-5f);
    float4 g  = reinterpret_cast<const float4*>(gamma)[t];
    float4 bt = reinterpret_cast<const float4*>(beta)[t];
    float o[4];
    o[0] = (v.x-mu)*inv*g.x + bt.x;
    o[1] = (v.y-mu)*inv*g.y + bt.y;
    o[2] = (v.z-mu)*inv*g.z + bt.z;
    o[3] = (v.w-mu)*inv*g.w + bt.w;
    bf16 h[4]; float l[4];
    #pragma unroll
    for (int j=0;j<4;j++){ h[j]=__float2bfloat16_rn(o[j]); l[j]=o[j]-__bfloat162float(h[j]); }
    bf162* ph = reinterpret_cast<bf162*>(xh + (size_t)row*EE + t*4);
    bf162* pl = reinterpret_cast<bf162*>(xl + (size_t)row*EE + t*4);
    ph[0] = bf162(h[0], h[1]);  ph[1] = bf162(h[2], h[3]);
    pl[0] = __floats2bfloat162_rn(l[0], l[1]);
    pl[1] = __floats2bfloat162_rn(l[2], l[3]);
}

// ---------------- 0.5*||row||^2 of bf16 q,k --------------------------------
__device__ __forceinline__ float sumsq8(uint4 u){
    float s = 0.f;
    uint32_t a[4] = {u.x, u.y, u.z, u.w};
    #pragma unroll
    for (int j=0;j<4;j++){
        float2 f = __bfloat1622float2(*reinterpret_cast<bf162*>(&a[j]));
        s += f.x*f.x + f.y*f.y;
    }
    return s;
}
__global__ __launch_bounds__(256) void xd_kernel(
    const bf16* __restrict__ q, const bf16* __restrict__ k,
    float* __restrict__ xdq, float* __restrict__ xdk)
{
    int row  = blockIdx.x*8 + (threadIdx.x>>5);
    int lane = threadIdx.x&31;
    const uint4* qr = reinterpret_cast<const uint4*>(q + (size_t)row*EE);
    const uint4* kr = reinterpret_cast<const uint4*>(k + (size_t)row*EE);
    float sq=0.f, sk=0.f;
    #pragma unroll
    for (int j=0;j<2;j++){
        sq += sumsq8(qr[lane + j*32]);
        sk += sumsq8(kr[lane + j*32]);
    }
    #pragma unroll
    for (int o=16;o>0;o>>=1){
        sq += __shfl_xor_sync(0xffffffffu, sq, o);
        sk += __shfl_xor_sync(0xffffffffu, sk, o);
    }
    if (lane==0){ xdq[row]=0.5f*sq; xdk[row]=0.5f*sk; }
}

// ---------------- column sums of kp (bf16) per batch -----------------------
__global__ __launch_bounds__(256) void ksum_kernel(
    const bf16* __restrict__ kp, float* __restrict__ out)
{
    int b = blockIdx.x, m0 = blockIdx.y*64;
    int tx = threadIdx.x & 63, ty = threadIdx.x >> 6;
    const bf16* base = kp + (size_t)b*SS*MF + m0 + tx;
    float s=0.f;
    for (int srow=ty; srow<SS; srow+=4) s += __bfloat162float(base[(size_t)srow*MF]);
    __shared__ float red[4][64];
    red[ty][tx]=s;
    __syncthreads();
    if (ty==0) out[b*MF+m0+tx] = red[0][tx]+red[1][tx]+red[2][tx]+red[3][tx];
}

// ---------------- batched 2D transpose with dtype convert ------------------
__device__ __forceinline__ float ldf(const float* p){ return *p; }
__device__ __forceinline__ float ldf(const bf16* p){ return __bfloat162float(*p); }
__device__ __forceinline__ void stf(float* p, float v){ *p = v; }
__device__ __forceinline__ void stf(bf16* p, float v){ *p = __float2bfloat16_rn(v); }

template<typename TI, typename TO>
__global__ __launch_bounds__(256) void transpose_t(
    const TI* __restrict__ in, TO* __restrict__ out, int R, int Cc)
{
    __shared__ float t[32][33];
    int z = blockIdx.z;
    in  += (size_t)z*R*Cc;
    out += (size_t)z*R*Cc;
    int tx = threadIdx.x & 31, ty = threadIdx.x >> 5;
    int x  = blockIdx.x*32 + tx;
    int y0 = blockIdx.y*32;
    #pragma unroll
    for (int j=0;j<4;j++)
        t[ty + j*8][tx] = ldf(in + (size_t)(y0 + ty + j*8)*Cc + x);
    __syncthreads();
    int xo = y0 + tx;
    int c0 = blockIdx.x*32;
    #pragma unroll
    for (int j=0;j<4;j++)
        stf(out + (size_t)(c0 + ty + j*8)*R + xo, t[tx][ty + j*8]);
}

// ---------------- reduce split-K partials -> bf16 --------------------------
__global__ __launch_bounds__(256) void reduce_kptv(
    const float* __restrict__ p, bf16* __restrict__ o)
{
    const size_t EM = (size_t)EE*MF;
    size_t i = (size_t)blockIdx.x*256 + threadIdx.x;
    int b = blockIdx.y;
    const float* pb = p + (size_t)b*SPLITK*EM + i;
    float s = 0.f;
    #pragma unroll
    for (int sk=0; sk<SPLITK; sk++) s += pb[(size_t)sk*EM];
    o[(size_t)b*EM + i] = __float2bfloat16_rn(s);
}

// ---------------- D[r] = qp[r,:] . ksum[b,:] -------------------------------
__global__ __launch_bounds__(256) void d_kernel(
    const bf16* __restrict__ qp, const float* __restrict__ ks,
    float* __restrict__ D)
{
    int row  = blockIdx.x*8 + (threadIdx.x>>5);
    int lane = threadIdx.x&31;
    int b = row >> 12;
    uint4 u = *reinterpret_cast<const uint4*>(qp + (size_t)row*MF + lane*8);
    float4 k0 = *reinterpret_cast<const float4*>(ks + b*MF + lane*8);
    float4 k1 = *reinterpret_cast<const float4*>(ks + b*MF + lane*8 + 4);
    uint32_t a[4] = {u.x, u.y, u.z, u.w};
    float kk[8] = {k0.x,k0.y,k0.z,k0.w,k1.x,k1.y,k1.z,k1.w};
    float s=0.f;
    #pragma unroll
    for (int j=0;j<4;j++){
        float2 f = __bfloat1622float2(*reinterpret_cast<bf162*>(&a[j]));
        s += f.x*kk[2*j] + f.y*kk[2*j+1];
    }
    #pragma unroll
    for (int o=16;o>0;o>>=1) s += __shfl_xor_sync(0xffffffffu, s, o);
    if (lane==0) D[row]=s;
}

// ---------------- launch ---------------------------------------------------
extern "C" void kernel_launch(void* const* d_in, const int* in_sizes, int n_in,
                              void* d_out, int out_size)
{
    const float* x     = (const float*)d_in[0];
    const float* qw    = (const float*)d_in[1];
    const float* qb    = (const float*)d_in[2];
    const float* kw    = (const float*)d_in[3];
    const float* kb    = (const float*)d_in[4];
    const float* vw    = (const float*)d_in[5];
    const float* vb    = (const float*)d_in[6];
    const float* pw    = (const float*)d_in[7];
    const float* pb    = (const float*)d_in[8];
    const float* gamma = (const float*)d_in[9];
    const float* beta  = (const float*)d_in[10];
    const float* w     = (const float*)d_in[11];
    float* out = (float*)d_out;

    bf16 *xnh,*xnl,*qbf,*kbf,*ybf,*vtb,*qpb,*kpb,*kptb,*kptvb;
    bf16 *qwb,*kwb,*pwb,*wb,*vwh,*vwl;
    float *v,*t1,*xdq,*xdk,*D,*ks,*kptvp;
    cudaGetSymbolAddress((void**)&xnh,  g_xnh);
    cudaGetSymbolAddress((void**)&xnl,  g_xnl);
    cudaGetSymbolAddress((void**)&qbf,  g_qb);
    cudaGetSymbolAddress((void**)&kbf,  g_kb);
    cudaGetSymbolAddress((void**)&ybf,  g_yb);
    cudaGetSymbolAddress((void**)&vtb,  g_vtb);
    cudaGetSymbolAddress((void**)&qpb,  g_qpb);
    cudaGetSymbolAddress((void**)&kpb,  g_kpb);
    cudaGetSymbolAddress((void**)&kptb, g_kptb);
    cudaGetSymbolAddress((void**)&kptvb,g_kptvb);
    cudaGetSymbolAddress((void**)&qwb,  g_qwb);
    cudaGetSymbolAddress((void**)&kwb,  g_kwb);
    cudaGetSymbolAddress((void**)&pwb,  g_pwb);
    cudaGetSymbolAddress((void**)&wb,   g_wb);
    cudaGetSymbolAddress((void**)&vwh,  g_vwh);
    cudaGetSymbolAddress((void**)&vwl,  g_vwl);
    cudaGetSymbolAddress((void**)&v,    g_v);
    cudaGetSymbolAddress((void**)&t1,   g_t1);
    cudaGetSymbolAddress((void**)&xdq,  g_xdq);
    cudaGetSymbolAddress((void**)&xdk,  g_xdk);
    cudaGetSymbolAddress((void**)&D,    g_D);
    cudaGetSymbolAddress((void**)&ks,   g_ks);
    cudaGetSymbolAddress((void**)&kptvp,g_kptvp);

    cudaFuncSetAttribute(gemm_bf<0>, cudaFuncAttributeMaxDynamicSharedMemorySize, SMEM_B);
    cudaFuncSetAttribute(gemm_bf<1>, cudaFuncAttributeMaxDynamicSharedMemorySize, SMEM_B);
    cudaFuncSetAttribute(gemm_bf<2>, cudaFuncAttributeMaxDynamicSharedMemorySize, SMEM_B);
    cudaFuncSetAttribute(gemm_bf<3>, cudaFuncAttributeMaxDynamicSharedMemorySize, SMEM_B);
    cudaFuncSetAttribute(gemm_bf<4>, cudaFuncAttributeMaxDynamicSharedMemorySize, SMEM_B);
    cudaFuncSetAttribute(gemm_bf<5>, cudaFuncAttributeMaxDynamicSharedMemorySize, SMEM_B);

    dim3 blk(256);

    // 0) weight conversions
    conv_b<<<EE*EE/256,blk>>>(qw, qwb, EE*EE);
    conv_b<<<EE*EE/256,blk>>>(kw, kwb, EE*EE);
    conv_b<<<EE*EE/256,blk>>>(pw, pwb, EE*EE);
    conv_b<<<MF*EE/256,blk>>>(w,  wb,  MF*EE);
    conv_split<<<EE*EE/256,blk>>>(vw, vwh, vwl, EE*EE);

    // 1) LayerNorm -> (xnh, xnl)
    ln_kernel<<<NR,128>>>(x, gamma, beta, xnh, xnl);

    // 2) q/k projections (bf16 out)
    dim3 gqkv(NR/128, EE/128, 1);
    gemm_bf<0><<<gqkv,blk,SMEM_B>>>(xnh, qwb, qbf, EE, EE, EE, EE, qb, nullptr, nullptr, nullptr, 0,0,0,0,1);
    gemm_bf<0><<<gqkv,blk,SMEM_B>>>(xnh, kwb, kbf, EE, EE, EE, EE, kb, nullptr, nullptr, nullptr, 0,0,0,0,1);

    // 3) v via split-bf16: t1 = xnh@vwl; t1 += xnl@vwh; v = xnh@vwh + vb + t1
    gemm_bf<4><<<gqkv,blk,SMEM_B>>>(xnh, vwl, t1, EE, EE, EE, EE, nullptr, nullptr, nullptr, nullptr, 0,0,0,0,1);
    gemm_bf<5><<<gqkv,blk,SMEM_B>>>(xnl, vwh, t1, EE, EE, EE, EE, nullptr, nullptr, nullptr, t1, 0,0,0,0,1);
    gemm_bf<3><<<gqkv,blk,SMEM_B>>>(xnh, vwh, v,  EE, EE, EE, EE, vb, nullptr, nullptr, t1, 0,0,0,0,1);

    // 4) row half-norms from bf16 q,k
    xd_kernel<<<NR/8,256>>>(qbf, kbf, xdq, xdk);

    // 5) features (exp epilogue, bf16 out)
    dim3 gqp(NR/128, MF/128, 1);
    gemm_bf<1><<<gqp,blk,SMEM_B>>>(qbf, wb, qpb, EE, EE, EE, MF, nullptr, xdq, nullptr, nullptr, 0,0,0,0,1);
    gemm_bf<1><<<gqp,blk,SMEM_B>>>(kbf, wb, kpb, EE, EE, EE, MF, nullptr, xdk, nullptr, nullptr, 0,0,0,0,1);

    // 6) ksum[b,m]
    ksum_kernel<<<dim3(BB, MF/64),blk>>>(kpb, ks);

    // 7) transposes: vtb[b][E][S] (f32->bf16), kptb[b][M][S] (bf16->bf16)
    transpose_t<float,bf16><<<dim3(EE/32, SS/32, BB),blk>>>(v,   vtb,  SS, EE);
    transpose_t<bf16,bf16> <<<dim3(MF/32, SS/32, BB),blk>>>(kpb, kptb, SS, MF);

    // 8) kptv split-K partials (f32), reduce -> bf16
    gemm_bf<4><<<dim3(EE/128, MF/128, BB*SPLITK),blk,SMEM_B>>>(
        vtb, kptb, kptvp, SS/SPLITK, SS, SS, MF, nullptr, nullptr, nullptr, nullptr,
        (size_t)EE*SS, (size_t)MF*SS, (size_t)EE*MF, 0, SPLITK);
    reduce_kptv<<<dim3((EE*MF)/256, BB),blk>>>(kptvp, kptvb);

    // 9) D[r]
    d_kernel<<<NR/8,256>>>(qpb, ks, D);

    // 10) y[b,s,e] = (qp @ kptv^T)/(D+eps), bf16 out
    gemm_bf<2><<<dim3(SS/128, EE/128, BB),blk,SMEM_B>>>(
        qpb, kptvb, ybf, MF, MF, MF, EE, nullptr, nullptr, D, nullptr,
        (size_t)SS*MF, (size_t)EE*MF, (size_t)SS*EE, SS, 1);

    // 11) out = v + y @ pw^T + pb   (f32 out)
    gemm_bf<3><<<gqkv,blk,SMEM_B>>>(ybf, pwb, out, EE, EE, EE, EE, pb, nullptr, nullptr, v, 0,0,0,0,1);
}